// round 10
// baseline (speedup 1.0000x reference)
#include <cuda_runtime.h>
#include <cuda_bf16.h>

// BBAStar: 8-connected grid shortest path, B=128, 32x32.
// R9: exact frontier Bellman-Ford in shared memory.
// Per pass: frontier cells scatter fl(w_v + d_u) to 8 neighbors via atomicMin
// on the int alias (positive floats: int order == IEEE order). fl(w+x) is
// monotone in x, so edge-wise relaxation has the same fixed point as the
// reference operator fl(w + exact-min8) => bit-exact float fixed point of the
// reference's 1024 Jacobi sweeps. Next frontier is built after a barrier by
// scanning 4 cells/thread against register snapshots (race-free dedupe).
// Empty frontier => no pending relaxations => exact fixed point.
// Padded 34x34 border with w=INF absorbs all bounds checks.
// Backtrack via precomputed argmin directions (OFFS first-occurrence tie-break).

#define BN 128
#define ST 35              // padded row stride
#define NPAD (34 * ST)
#define INF_F 1000000000.0f
#define EPS_F 1e-6f

__device__ __forceinline__ int pick8(float a0, float a1, float a2, float a3,
                                     float a4, float a5, float a6, float a7) {
    float bb = a0; int bd = 0;
    if (a1 < bb) { bb = a1; bd = 1; }
    if (a2 < bb) { bb = a2; bd = 2; }
    if (a3 < bb) { bb = a3; bd = 3; }
    if (a4 < bb) { bb = a4; bd = 4; }
    if (a5 < bb) { bb = a5; bd = 5; }
    if (a6 < bb) { bb = a6; bd = 6; }
    if (a7 < bb) { bb = a7; bd = 7; }
    return bd;
}

__global__ void __launch_bounds__(256, 1)
bba_kernel(const float* __restrict__ weights,
           const int*   __restrict__ source,
           const int*   __restrict__ target,
           float*       __restrict__ out)
{
    __shared__ float dist[NPAD];            // padded 34x34
    __shared__ float wpad[NPAD];            // padded weights, border = INF
    __shared__ unsigned short lists[2][1024];
    __shared__ int cnt[2];
    __shared__ int nbr[1024];

    int* idist = (int*)dist;

    const int b   = blockIdx.x;
    const int tid = threadIdx.x;

    // Init padded arrays.
    for (int i = tid; i < NPAD; i += 256) { dist[i] = INF_F; wpad[i] = INF_F; }

    // Coalesced weight load (+EPS, reference float32 math).
    const float* wb = weights + (b << 10);
    float wreg[4];
    #pragma unroll
    for (int k = 0; k < 4; ++k) wreg[k] = wb[k * 256 + tid] + EPS_F;

    const int sr = source[2 * b + 0];
    const int sc = source[2 * b + 1];
    const int tr = target[2 * b + 0];
    const int tc = target[2 * b + 1];

    // Zero the poisoned output slice.
    #pragma unroll
    for (int k = 0; k < 4; ++k) out[(b << 10) + k * 256 + tid] = 0.0f;

    if (tid == 0) { cnt[0] = 0; cnt[1] = 0; }
    __syncthreads();                         // INF init done before interior fill

    // Interior weights into the padded array (coalesced smem stores).
    int own[4];
    #pragma unroll
    for (int k = 0; k < 4; ++k) {
        int i = k * 256 + tid;               // interior linear cell id
        own[k] = ((i >> 5) + 1) * ST + (i & 31) + 1;
        wpad[own[k]] = wreg[k];
    }
    __syncthreads();

    const int spidx = (sr + 1) * ST + (sc + 1);
    if (tid == 0) {
        dist[spidx] = wpad[spidx];           // dist0[source] = w[source]
        lists[0][0] = (unsigned short)spidx;
        cnt[0] = 1;
    }
    __syncthreads();

    // Register snapshots for change detection (source owner picks up ws).
    float prev[4];
    #pragma unroll
    for (int k = 0; k < 4; ++k) prev[k] = dist[own[k]];

    // OFFS-order neighbor offsets: (-1,-1),(-1,0),(-1,1),(0,-1),(0,1),(1,-1),(1,0),(1,1)
    const int off8[8] = {-ST - 1, -ST, -ST + 1, -1, 1, ST - 1, ST, ST + 1};

    // Frontier Bellman-Ford.
    int cur = 0;
    for (;;) {
        const int n = cnt[cur];
        if (n == 0) break;                   // no pending relaxations => fixed pt

        // Scatter: relax all 8 edges out of each frontier cell.
        for (int i = tid; i < n; i += 256) {
            const int u = lists[cur][i];
            const float du = dist[u];        // stale-high is safe: re-enqueued if lowered
            #pragma unroll
            for (int j = 0; j < 8; ++j) {
                const int v = u + off8[j];
                const float cand = wpad[v] + du;   // border: INF + du >= INF -> no-op
                atomicMin(&idist[v], __float_as_int(cand));
            }
        }
        __syncthreads();                     // all scatters visible

        // Scan: build next frontier from changed cells (exact dedupe).
        const int nx = cur ^ 1;
        #pragma unroll
        for (int k = 0; k < 4; ++k) {
            const float f = dist[own[k]];
            if (f < prev[k]) {
                prev[k] = f;
                const int p = atomicAdd(&cnt[nx], 1);
                lists[nx][p] = (unsigned short)own[k];
            }
        }
        if (tid == 0) cnt[cur] = 0;
        __syncthreads();                     // enqueues + reset visible
        cur = nx;
    }

    // Parallel argmin-neighbor directions, OFFS order (border INF reproduces
    // the reference's invalid->INF masking; strict '<' = first-occurrence).
    #pragma unroll
    for (int k = 0; k < 4; ++k) {
        const int u = own[k];
        nbr[k * 256 + tid] = pick8(dist[u - ST - 1], dist[u - ST], dist[u - ST + 1],
                                   dist[u - 1],                    dist[u + 1],
                                   dist[u + ST - 1], dist[u + ST], dist[u + ST + 1]);
    }
    __syncthreads();

    // Serial backtrack: follow precomputed directions.
    if (tid == 0) {
        const int drs[8] = {-1, -1, -1,  0, 0,  1, 1, 1};
        const int dcs[8] = {-1,  0,  1, -1, 1, -1, 0, 1};
        int cr = tr, cc = tc;
        float* o = out + (b << 10);
        for (int step = 0; step < 1024; ++step) {
            o[(cr << 5) + cc] = 1.0f;
            if (cr == sr && cc == sc) break;
            const int k = nbr[(cr << 5) + cc];
            cr += drs[k];
            cc += dcs[k];
        }
    }
}

extern "C" void kernel_launch(void* const* d_in, const int* in_sizes, int n_in,
                              void* d_out, int out_size)
{
    const float* weights = (const float*)d_in[0];
    const int*   source  = (const int*)d_in[1];
    const int*   target  = (const int*)d_in[2];
    float*       out     = (float*)d_out;

    bba_kernel<<<BN, 256>>>(weights, source, target, out);
}

// round 11
// speedup vs baseline: 1.7912x; 1.7912x over previous
#include <cuda_runtime.h>
#include <cuda_bf16.h>

// BBAStar: 8-connected grid shortest path, B=128, 32x32.
// R10: R6 structure with FAT bands — 128 threads, 4 warps, 8-row (V) /
// 8-col (H) bands, KP=2. Per-phase GS reach ~16-24 rows => fewer epochs;
// the SM's idle issue slots are traded for propagation reach.
// Monotone relaxation with the exact reference operator fl(w + exact-min8)
// => bit-exact float fixed point of the reference's 1024 Jacobi sweeps.
// Zero-change epoch (V phase applies the full operator to every cell) =>
// fixed point verified. Backtrack follows precomputed argmin-neighbor
// LINEAR DELTAS (OFFS first-occurrence tie-break), LDS+IADD per step.

#define BN 128
#define ST 35              // smem row stride (odd => conflict-free both axes)
#define INF_F 1000000000.0f
#define EPS_F 1e-6f
#define NB 8               // band height
#define KP 2               // fwd+bwd sweep pairs per phase

__device__ __forceinline__ float shl(float v, int lane) {
    float t = __shfl_up_sync(0xffffffffu, v, 1);
    return (lane == 0) ? INF_F : t;
}
__device__ __forceinline__ float shr(float v, int lane) {
    float t = __shfl_down_sync(0xffffffffu, v, 1);
    return (lane == 31) ? INF_F : t;
}
__device__ __forceinline__ float min8f(float a, float b, float c, float d,
                                       float e, float f, float g, float h) {
    return fminf(fminf(fminf(a, b), fminf(c, d)),
                 fminf(fminf(e, f), fminf(g, h)));
}
// OFFS-order first-occurrence argmin; returns LINEAR delta (dr*32+dc).
__device__ __forceinline__ int pick8d(float a0, float a1, float a2, float a3,
                                      float a4, float a5, float a6, float a7) {
    float bb = a0; int bd = -33;
    if (a1 < bb) { bb = a1; bd = -32; }
    if (a2 < bb) { bb = a2; bd = -31; }
    if (a3 < bb) { bb = a3; bd = -1; }
    if (a4 < bb) { bb = a4; bd = 1; }
    if (a5 < bb) { bb = a5; bd = 31; }
    if (a6 < bb) { bb = a6; bd = 32; }
    if (a7 < bb) { bb = a7; bd = 33; }
    return bd;
}

// Forward GS sweep over NB owned lines (fresh prev-line shfls on the chain;
// current-line shfls inherited from the previous line's next-line shfls).
__device__ __forceinline__ void sweep_fwd(volatile float* vd, const float (&w)[NB],
                                          float (&d)[NB], int i0, int di,
                                          int ix, int iy, int lane, bool& any)
{
    float X = vd[ix], Y = vd[iy];
    float p = X, pl = shl(X, lane), pr = shr(X, lane);
    float cl = shl(d[0], lane), cr = shr(d[0], lane);
    #pragma unroll
    for (int i = 0; i < NB; ++i) {
        float nx = (i < NB - 1) ? d[i + 1] : Y;
        float nl = shl(nx, lane), nr = shr(nx, lane);
        float v = w[i] + min8f(pl, p, pr, cl, cr, nl, nx, nr);
        if (v < d[i]) { d[i] = v; vd[i0 + i * di] = v; any = true; }
        p = d[i]; pl = shl(p, lane); pr = shr(p, lane);
        cl = nl; cr = nr;
    }
}
__device__ __forceinline__ void sweep_bwd(volatile float* vd, const float (&w)[NB],
                                          float (&d)[NB], int i0, int di,
                                          int ix, int iy, int lane, bool& any)
{
    float X = vd[ix], Y = vd[iy];
    float p = Y, pl = shl(Y, lane), pr = shr(Y, lane);
    float cl = shl(d[NB - 1], lane), cr = shr(d[NB - 1], lane);
    #pragma unroll
    for (int i = NB - 1; i >= 0; --i) {
        float nx = (i > 0) ? d[i - 1] : X;
        float nl = shl(nx, lane), nr = shr(nx, lane);
        float v = w[i] + min8f(nl, nx, nr, cl, cr, pl, p, pr);
        if (v < d[i]) { d[i] = v; vd[i0 + i * di] = v; any = true; }
        p = d[i]; pl = shl(p, lane); pr = shr(p, lane);
        cl = nl; cr = nr;
    }
}

__global__ void __launch_bounds__(128, 1)
bba_kernel(const float* __restrict__ weights,
           const int*   __restrict__ source,
           const int*   __restrict__ target,
           float*       __restrict__ out)
{
    __shared__ float dist[34 * ST];     // padded 34x34, stride 35
    __shared__ float wsh[32][33];       // weights, conflict-free both axes
    __shared__ int   nbr[1024];         // linear step deltas
    volatile float* vd = dist;

    const int b    = blockIdx.x;
    const int tid  = threadIdx.x;
    const int wpid = tid >> 5;          // warp id 0..3
    const int lane = tid & 31;
    const int g0   = NB * wpid;         // band start (row for V / col for H)

    // Weights (+EPS), coalesced; stash for both layouts.
    const float* wb = weights + (b << 10);
    float wv[NB], wh[NB];
    #pragma unroll
    for (int i = 0; i < NB; ++i) {
        wv[i] = wb[((g0 + i) << 5) + lane] + EPS_F;
        wsh[g0 + i][lane] = wv[i];
    }

    const int sr = source[2 * b + 0];
    const int sc = source[2 * b + 1];
    const int tr = target[2 * b + 0];
    const int tc = target[2 * b + 1];

    // Zero the poisoned output slice.
    #pragma unroll
    for (int k = 0; k < 8; ++k) out[(b << 10) + (k << 7) + tid] = 0.0f;

    for (int i = tid; i < 34 * ST; i += 128) dist[i] = INF_F;
    __syncthreads();

    #pragma unroll
    for (int i = 0; i < NB; ++i) wh[i] = wsh[lane][g0 + i];
    if (tid == 0) dist[(sr + 1) * ST + (sc + 1)] = wsh[sr][sc];
    __syncthreads();

    const int v_i0 = (g0 + 1) * ST + (lane + 1);
    const int v_ix = (g0 + 0) * ST + (lane + 1);
    const int v_iy = (g0 + NB + 1) * ST + (lane + 1);
    const int h_i0 = (lane + 1) * ST + (g0 + 1);
    const int h_ix = (lane + 1) * ST + (g0 + 0);
    const int h_iy = (lane + 1) * ST + (g0 + NB + 1);

    float d[NB];

    for (;;) {
        bool any = false;

        // V phase: reload own rows, KP fwd+bwd GS sweep pairs.
        #pragma unroll
        for (int i = 0; i < NB; ++i) d[i] = vd[v_i0 + i * ST];
        #pragma unroll 1
        for (int k = 0; k < KP; ++k) {
            sweep_fwd(vd, wv, d, v_i0, ST, v_ix, v_iy, lane, any);
            sweep_bwd(vd, wv, d, v_i0, ST, v_ix, v_iy, lane, any);
        }

        __syncthreads();                 // V writes visible to H phase

        // H phase: reload own cols, KP fwd+bwd GS sweep pairs.
        #pragma unroll
        for (int i = 0; i < NB; ++i) d[i] = vd[h_i0 + i];
        #pragma unroll 1
        for (int k = 0; k < KP; ++k) {
            sweep_fwd(vd, wh, d, h_i0, 1, h_ix, h_iy, lane, any);
            sweep_bwd(vd, wh, d, h_i0, 1, h_ix, h_iy, lane, any);
        }

        if (!__syncthreads_or((int)any)) break;   // zero-change epoch => d*
    }

    // Parallel argmin-neighbor deltas (V layout), OFFS order:
    // (-1,-1),(-1,0),(-1,1),(0,-1),(0,1),(1,-1),(1,0),(1,1)
    {
        #pragma unroll
        for (int i = 0; i < NB; ++i) d[i] = vd[v_i0 + i * ST];
        float up[NB + 2], dnl[NB + 2], dnr[NB + 2];  // rows g0-1 .. g0+NB
        up[0] = vd[v_ix];
        #pragma unroll
        for (int i = 0; i < NB; ++i) up[i + 1] = d[i];
        up[NB + 1] = vd[v_iy];
        #pragma unroll
        for (int i = 0; i < NB + 2; ++i) {
            dnl[i] = shl(up[i], lane);
            dnr[i] = shr(up[i], lane);
        }
        #pragma unroll
        for (int i = 0; i < NB; ++i) {
            nbr[((g0 + i) << 5) + lane] =
                pick8d(dnl[i],     up[i],     dnr[i],
                       dnl[i + 1],            dnr[i + 1],
                       dnl[i + 2], up[i + 2], dnr[i + 2]);
        }
    }
    __syncthreads();

    // Serial backtrack: idx += nbr[idx] per step (LDS + IADD chain).
    if (tid == 0) {
        int idx  = (tr << 5) + tc;
        const int sidx = (sr << 5) + sc;
        float* o = out + (b << 10);
        for (int step = 0; step < 1024; ++step) {
            o[idx] = 1.0f;
            if (idx == sidx) break;
            idx += nbr[idx];
        }
    }
}

extern "C" void kernel_launch(void* const* d_in, const int* in_sizes, int n_in,
                              void* d_out, int out_size)
{
    const float* weights = (const float*)d_in[0];
    const int*   source  = (const int*)d_in[1];
    const int*   target  = (const int*)d_in[2];
    float*       out     = (float*)d_out;

    bba_kernel<<<BN, 128>>>(weights, source, target, out);
}